// round 16
// baseline (speedup 1.0000x reference)
#include <cuda_runtime.h>
#include <cuda_fp16.h>
#include <cuda_bf16.h>

// Problem constants
#define BB 8
#define CC 32
#define TT 12
#define NNODE 5000
#define EDGES 80000
#define FF (BB*TT*CC)       // 3072 features per node
#define BT (BB*TT)          // 96
#define EPAD (EDGES + NNODE*3 + 8)  // padded CSR capacity (pad-to-4)

#define NTILES 157                  // ceil(5000/32)
#define YBLOCKS (NTILES * (BT/8))   // 157*12 = 1884 y-blocks
#define PREPB 120                   // resident prep blocks (phase-barriered)
#define AGGBLOCKS 592               // persistent k_agg blocks (~4/SM)

// ---------------------------------------------------------------------------
// Scratch (static __device__ arrays — no allocations allowed).
// Counters zeroed after last use each call; first call relies on zero-init.
// g_y row NNODE (dummy) is NEVER written -> stays zero from static init.
// ---------------------------------------------------------------------------
__device__ __align__(16) __half g_y  [(size_t)(NNODE + 1) * FF]; // +1 dummy zero row
__device__ __align__(16) __half g_agg[(size_t)NNODE * FF];
__device__ int    g_deg_in [NNODE];
__device__ int    g_deg_out[NNODE];
__device__ int    g_cursor [NNODE];
__device__ int    g_ptr    [NNODE + 1];          // padded CSR row ptr by dst
__device__ __align__(16) unsigned g_csr[EPAD];   // (fp16 ns_src << 16) | src
__device__ float  g_norm_src[NNODE];
__device__ float  g_norm_dst[NNODE];
__device__ int    g_work;                        // k_agg work-stealing counter
__device__ int    g_bar_cnt;                     // prep phase barrier counter

// W staged in constant memory: warp-uniform reads go through the separate
// uniform-constant port (LDCU, floor 1/cyc) instead of the L1/LSU crossbar.
// Filled each call by a graph-capturable d2d memcpy in kernel_launch.
__constant__ __align__(16) float cW[CC * CC];

// Packed 2xfp32 FMA (Blackwell FFMA2 — only reachable via PTX f32x2)
__device__ __forceinline__ unsigned long long ffma2(
    unsigned long long a, unsigned long long b, unsigned long long c) {
    unsigned long long d;
    asm("fma.rn.f32x2 %0, %1, %2, %3;" : "=l"(d) : "l"(a), "l"(b), "l"(c));
    return d;
}

// Phase barrier for the PREPB resident blocks. Not a deadlock risk: prep
// blocks are blockIdx 0..119 (all wave-1 resident), y-blocks never wait.
__device__ __forceinline__ void prep_bar(int target) {
    __syncthreads();
    if (threadIdx.x == 0) {
        __threadfence();
        atomicAdd(&g_bar_cnt, 1);
        while (atomicAdd(&g_bar_cnt, 0) < target) __nanosleep(64);
    }
    __syncthreads();
}

// build half2(ns, ns) from packed CSR word (ns fp16 bits in [31:16])
__device__ __forceinline__ __half2 mkns2(unsigned u) {
    unsigned r = (u & 0xFFFF0000u) | (u >> 16);
    return *reinterpret_cast<__half2*>(&r);
}

// ---------------------------------------------------------------------------
// K1: ONE kernel = prep chain (120 barriered blocks) + y'-GEMM (1884 blocks).
// y branch: thread = (16 c' columns) x (2 bt); W operands from constant
// memory (uniform port) -> LSU carries only x LDG + y STG. No smem, no sync.
// y' = xW (UNNORMALIZED; norm_src applied in k_agg via packed fp16 ns).
// ---------------------------------------------------------------------------
__global__ __launch_bounds__(256, 4)
void k_prep_y(const float* __restrict__ x,
              const int* __restrict__ src, const int* __restrict__ dst) {
    if (blockIdx.x < PREPB) {
        // ================= prep branch =================
        const int tid  = threadIdx.x;
        const int gtid = blockIdx.x * 256 + tid;

        // phase A: degree histograms (distributed global atomics)
        for (int e = gtid; e < EDGES; e += PREPB * 256) {
            atomicAdd(&g_deg_out[src[e]], 1);
            atomicAdd(&g_deg_in [dst[e]], 1);
        }
        prep_bar(PREPB);

        // phase B: block 0 only — norms + padded exclusive scan
        if (blockIdx.x == 0) {
            __shared__ int s_wsum[8];
            const int lane = tid & 31;
            const int warp = tid >> 5;

            if (tid == 0) g_work = 0;

            for (int i = tid; i < NNODE; i += 256) {
                g_norm_src[i] = rsqrtf((float)max(g_deg_out[i], 1));
                g_norm_dst[i] = rsqrtf((float)max(g_deg_in [i], 1));
            }

            // scan of pad-4 degrees: 20 nodes/thread (256*20 = 5120)
            const int base = tid * 20;
            int pd[20];
            int tsum = 0;
            #pragma unroll
            for (int k = 0; k < 20; k++) {
                int dg = (base + k < NNODE) ? g_deg_in[base + k] : 0;
                pd[k] = (dg + 3) & ~3;
                tsum += pd[k];
            }
            int incl = tsum;
            #pragma unroll
            for (int off = 1; off < 32; off <<= 1) {
                int t = __shfl_up_sync(0xffffffffu, incl, off);
                if (lane >= off) incl += t;
            }
            if (lane == 31) s_wsum[warp] = incl;
            __syncthreads();
            if (tid == 0) {
                int r = 0;
                #pragma unroll
                for (int w = 0; w < 8; w++) { int t = s_wsum[w]; s_wsum[w] = r; r += t; }
            }
            __syncthreads();

            int run = s_wsum[warp] + incl - tsum;
            #pragma unroll
            for (int k = 0; k < 20; k++) {
                int idx = base + k;
                if (idx < NNODE) { g_ptr[idx] = run; run += pd[k]; }
            }
            if (tid == (NNODE + 19) / 20 - 1) g_ptr[NNODE] = run;
        }
        prep_bar(2 * PREPB);

        // phase C: scatter (pack fp16 norm_src into bits [31:16]) + pad fill
        for (int e = gtid; e < EDGES; e += PREPB * 256) {
            int s = src[e], d = dst[e];
            int pos = __ldcg(&g_ptr[d]) + atomicAdd(&g_cursor[d], 1);
            unsigned nsb = (unsigned)__half_as_ushort(
                               __float2half_rn(__ldcg(&g_norm_src[s])));
            g_csr[pos] = (unsigned)s | (nsb << 16);
        }
        for (int i = gtid; i < NNODE; i += PREPB * 256) {
            int p  = __ldcg(&g_ptr[i]);
            int dg = __ldcg(&g_deg_in[i]);
            int pad = (dg + 3) & ~3;
            for (int j = dg; j < pad; j++) g_csr[p + j] = NNODE;  // ns=0, zero row
        }
        return;
    }

    // ================= y' branch (no prep dependency, no smem) =============
    int tid = threadIdx.x;
    int tx = tid & 31, ty = tid >> 5;

    int yb  = blockIdx.x - PREPB;
    int nt  = yb % NTILES;
    int btt = yb / NTILES;
    int n   = nt * 32 + tx;
    if (n >= NNODE) return;

    const int h   = ty & 1;          // c' half: columns [h*16, h*16+16)
    const int bp  = ty >> 1;         // bt-pair slot 0..3
    const int bt0 = btt * 8 + bp * 2;
    const int bt1 = bt0 + 1;
    const int b0 = bt0 / TT, t0 = bt0 - b0 * TT;
    const int b1 = bt1 / TT, t1 = bt1 - b1 * TT;

    const size_t cstride = (size_t)TT * NNODE;
    const float* xpA = x + ((size_t)b0 * CC * TT) * NNODE + (size_t)t0 * NNODE + n;
    const float* xpB = x + ((size_t)b1 * CC * TT) * NNODE + (size_t)t1 * NNODE + n;

    unsigned long long accA[8], accB[8];
    #pragma unroll
    for (int j = 0; j < 8; j++) { accA[j] = 0ull; accB[j] = 0ull; }

    // software-pipelined c-loop: 8 chunks of 4, double-buffered x loads
    float xaA[4], xaB[4], xnA[4], xnB[4];
    #pragma unroll
    for (int k = 0; k < 4; k++) {
        xaA[k] = __ldcs(xpA + (size_t)k * cstride);
        xaB[k] = __ldcs(xpB + (size_t)k * cstride);
        xnA[k] = 0.0f; xnB[k] = 0.0f;
    }

    #pragma unroll
    for (int ch = 0; ch < 8; ch++) {
        if (ch < 7) {
            #pragma unroll
            for (int k = 0; k < 4; k++) {
                xnA[k] = __ldcs(xpA + (size_t)(ch * 4 + 4 + k) * cstride);
                xnB[k] = __ldcs(xpB + (size_t)(ch * 4 + 4 + k) * cstride);
            }
        }
        #pragma unroll
        for (int kc = 0; kc < 4; kc++) {
            int c = ch * 4 + kc;
            unsigned long long xvA, xvB;
            asm("mov.b64 %0, {%1, %1};" : "=l"(xvA) : "f"(xaA[kc]));
            asm("mov.b64 %0, {%1, %1};" : "=l"(xvB) : "f"(xaB[kc]));
            // 16 W floats for this (c, h) from CONSTANT memory (uniform port)
            const ulonglong2* wr =
                reinterpret_cast<const ulonglong2*>(cW + c * CC + h * 16);
            #pragma unroll
            for (int q = 0; q < 4; q++) {
                ulonglong2 w = wr[q];
                accA[2*q]     = ffma2(xvA, w.x, accA[2*q]);
                accB[2*q]     = ffma2(xvB, w.x, accB[2*q]);
                accA[2*q + 1] = ffma2(xvA, w.y, accA[2*q + 1]);
                accB[2*q + 1] = ffma2(xvB, w.y, accB[2*q + 1]);
            }
        }
        #pragma unroll
        for (int k = 0; k < 4; k++) { xaA[k] = xnA[k]; xaB[k] = xnB[k]; }
    }

    // pack fp16 (unnormalized) and store: 16 c' x 2 bt = 2x2 uint4
    unsigned oA[8], oB[8];
    #pragma unroll
    for (int j = 0; j < 8; j++) {
        float lo, hi;
        asm("mov.b64 {%0, %1}, %2;" : "=f"(lo), "=f"(hi) : "l"(accA[j]));
        __half2 hh = __floats2half2_rn(lo, hi);
        oA[j] = *reinterpret_cast<unsigned*>(&hh);
        asm("mov.b64 {%0, %1}, %2;" : "=f"(lo), "=f"(hi) : "l"(accB[j]));
        hh = __floats2half2_rn(lo, hi);
        oB[j] = *reinterpret_cast<unsigned*>(&hh);
    }
    uint4* ypA = reinterpret_cast<uint4*>(
        g_y + (size_t)n * FF + (size_t)bt0 * CC + h * 16);
    uint4* ypB = reinterpret_cast<uint4*>(
        g_y + (size_t)n * FF + (size_t)bt1 * CC + h * 16);
    ypA[0] = make_uint4(oA[0], oA[1], oA[2], oA[3]);
    ypA[1] = make_uint4(oA[4], oA[5], oA[6], oA[7]);
    ypB[0] = make_uint4(oB[0], oB[1], oB[2], oB[3]);
    ypB[1] = make_uint4(oB[4], oB[5], oB[6], oB[7]);
}

// ---------------------------------------------------------------------------
// K2: persistent work-stealing aggregation.
// agg[d] = norm_dst[d] * sum_e ns_src(e) * y'[src(e)]
// 8-edge main loop (8-deep MLP), two independent 4-edge HFMA2 chains with
// per-edge ns from the packed CSR word. fp32 upconvert per chain; 4-edge
// tail. Zeroes counters + barrier counter for next replay.
// ---------------------------------------------------------------------------
__global__ __launch_bounds__(384)
void k_agg() {
    __shared__ int s_d;
    int tid = threadIdx.x;
    if (blockIdx.x == 0 && tid == 0) g_bar_cnt = 0;   // reset prep barrier

    while (true) {
        if (tid == 0) s_d = atomicAdd(&g_work, 1);
        __syncthreads();
        int d = s_d;
        __syncthreads();
        if (d >= NNODE) return;

        if (tid == 0) {
            g_deg_in[d] = 0;
            g_deg_out[d] = 0;
            g_cursor[d] = 0;
        }

        int beg = g_ptr[d], end = g_ptr[d + 1];   // multiple of 4, 16B-aligned

        float2 acc[4];
        #pragma unroll
        for (int j = 0; j < 4; j++) acc[j] = make_float2(0.f, 0.f);

        int g0 = beg;
        for (; g0 + 8 <= end; g0 += 8) {
            uint4 i0 = *reinterpret_cast<const uint4*>(&g_csr[g0]);
            uint4 i1 = *reinterpret_cast<const uint4*>(&g_csr[g0 + 4]);
            unsigned u[8] = { i0.x, i0.y, i0.z, i0.w, i1.x, i1.y, i1.z, i1.w };
            uint4 v[8];
            #pragma unroll
            for (int k = 0; k < 8; k++)
                v[k] = reinterpret_cast<const uint4*>(
                           g_y + (size_t)(u[k] & 0xFFFFu) * FF)[tid];
            __half2 ha[4], hb[4];
            #pragma unroll
            for (int j = 0; j < 4; j++) {
                ha[j] = __floats2half2_rn(0.f, 0.f);
                hb[j] = __floats2half2_rn(0.f, 0.f);
            }
            #pragma unroll
            for (int k = 0; k < 4; k++) {
                __half2 nA = mkns2(u[k]);
                __half2 nB = mkns2(u[k + 4]);
                #pragma unroll
                for (int j = 0; j < 4; j++) {
                    ha[j] = __hfma2(*reinterpret_cast<const __half2*>(&(&v[k].x)[j]),
                                    nA, ha[j]);
                    hb[j] = __hfma2(*reinterpret_cast<const __half2*>(&(&v[k+4].x)[j]),
                                    nB, hb[j]);
                }
            }
            #pragma unroll
            for (int j = 0; j < 4; j++) {
                float2 fa = __half22float2(ha[j]);
                float2 fb = __half22float2(hb[j]);
                acc[j].x += fa.x + fb.x;
                acc[j].y += fa.y + fb.y;
            }
        }
        if (g0 < end) {            // tail: one group of 4
            uint4 i0 = *reinterpret_cast<const uint4*>(&g_csr[g0]);
            unsigned u[4] = { i0.x, i0.y, i0.z, i0.w };
            uint4 v[4];
            #pragma unroll
            for (int k = 0; k < 4; k++)
                v[k] = reinterpret_cast<const uint4*>(
                           g_y + (size_t)(u[k] & 0xFFFFu) * FF)[tid];
            #pragma unroll
            for (int j = 0; j < 4; j++) {
                __half2 h = __floats2half2_rn(0.f, 0.f);
                #pragma unroll
                for (int k = 0; k < 4; k++)
                    h = __hfma2(*reinterpret_cast<const __half2*>(&(&v[k].x)[j]),
                                mkns2(u[k]), h);
                float2 f = __half22float2(h);
                acc[j].x += f.x; acc[j].y += f.y;
            }
        }

        float nd = g_norm_dst[d];
        __half2 o[4];
        #pragma unroll
        for (int j = 0; j < 4; j++)
            o[j] = __floats2half2_rn(acc[j].x * nd, acc[j].y * nd);
        uint4 pack;
        pack.x = *reinterpret_cast<unsigned*>(&o[0]);
        pack.y = *reinterpret_cast<unsigned*>(&o[1]);
        pack.z = *reinterpret_cast<unsigned*>(&o[2]);
        pack.w = *reinterpret_cast<unsigned*>(&o[3]);
        reinterpret_cast<uint4*>(g_agg + (size_t)d * FF)[tid] = pack;
    }
}

// ---------------------------------------------------------------------------
// K3: out[b,c,t,n] = relu(x[b,c,t,n] + bias[c] + agg[n][b][t][c])
// ---------------------------------------------------------------------------
#define ONODES 256
__global__ __launch_bounds__(512, 3)
void k_out(const float* __restrict__ x, const float* __restrict__ bias,
           float* __restrict__ out) {
    __shared__ float s[CC][ONODES + 4];
    int bt = blockIdx.y;
    int b = bt / TT, t = bt - b * TT;
    int n0 = blockIdx.x * ONODES;
    int tid = threadIdx.y * 64 + threadIdx.x;

    {
        int nl   = tid >> 1;
        int part = tid & 1;
        int n = n0 + nl;
        if (n < NNODE) {
            const uint4* ar =
                reinterpret_cast<const uint4*>(g_agg + (size_t)n * FF + (size_t)bt * CC);
            #pragma unroll
            for (int q = 0; q < 2; q++) {
                uint4 v = ar[part * 2 + q];
                int c0 = part * 16 + q * 8;
                const unsigned* u = &v.x;
                #pragma unroll
                for (int j = 0; j < 4; j++) {
                    float2 f = __half22float2(*reinterpret_cast<const __half2*>(&u[j]));
                    s[c0 + 2*j    ][nl] = f.x;
                    s[c0 + 2*j + 1][nl] = f.y;
                }
            }
        }
    }
    __syncthreads();

    int n4 = threadIdx.x * 4;
    int n = n0 + n4;
    if (n < NNODE) {
        #pragma unroll
        for (int k = 0; k < 4; k++) {
            int c = threadIdx.y + k * 8;
            float bc = bias[c];
            size_t idx = (((size_t)b * CC + c) * TT + t) * NNODE + n;
            float4 xv = __ldcs(reinterpret_cast<const float4*>(x + idx));
            float4 av = *reinterpret_cast<const float4*>(&s[c][n4]);
            float4 r;
            r.x = fmaxf(xv.x + bc + av.x, 0.f);
            r.y = fmaxf(xv.y + bc + av.y, 0.f);
            r.z = fmaxf(xv.z + bc + av.z, 0.f);
            r.w = fmaxf(xv.w + bc + av.w, 0.f);
            __stcs(reinterpret_cast<float4*>(out + idx), r);
        }
    }
}

// ---------------------------------------------------------------------------
// Launch: d2d memcpy (W -> constant bank) + 3 kernels. The memcpy is
// device-to-device and async -> graph-capturable, no allocation.
// ---------------------------------------------------------------------------
extern "C" void kernel_launch(void* const* d_in, const int* in_sizes, int n_in,
                              void* d_out, int out_size) {
    const float* x    = (const float*)d_in[0];  // [B, C, T, N]
    const float* W    = (const float*)d_in[1];  // [C, C]
    const float* bias = (const float*)d_in[2];  // [C]
    const int*   src  = (const int*)d_in[3];    // [E]
    const int*   dst  = (const int*)d_in[4];    // [E]
    float*       out  = (float*)d_out;          // [B, C, T, N]

    cudaMemcpyToSymbolAsync(cW, W, CC * CC * sizeof(float), 0,
                            cudaMemcpyDeviceToDevice, 0);
    k_prep_y<<<PREPB + YBLOCKS, 256>>>(x, src, dst);
    k_agg<<<AGGBLOCKS, 384>>>();
    k_out<<<dim3((NNODE + ONODES - 1) / ONODES, BT), dim3(64, 8)>>>(x, bias, out);
}

// round 17
// speedup vs baseline: 1.0362x; 1.0362x over previous
#include <cuda_runtime.h>
#include <cuda_fp16.h>
#include <cuda_bf16.h>

// Problem constants
#define BB 8
#define CC 32
#define TT 12
#define NNODE 5000
#define EDGES 80000
#define FF (BB*TT*CC)       // 3072 features per node
#define BT (BB*TT)          // 96
#define EPAD (EDGES + NNODE*3 + 8)  // padded CSR capacity (pad-to-4)

#define NTILES 157                  // ceil(5000/32)
#define YBLOCKS (NTILES * (BT/16))  // 157*6 = 942 y-blocks (16 bt per block)
#define PREPB 120                   // resident prep blocks (phase-barriered)
#define AGGBLOCKS 592               // persistent k_agg blocks (~4/SM)

// ---------------------------------------------------------------------------
// Scratch (static __device__ arrays — no allocations allowed).
// Counters zeroed after last use each call; first call relies on zero-init.
// g_y row NNODE (dummy) is NEVER written -> stays zero from static init.
// ---------------------------------------------------------------------------
__device__ __align__(16) __half g_y  [(size_t)(NNODE + 1) * FF]; // +1 dummy zero row
__device__ __align__(16) __half g_agg[(size_t)NNODE * FF];
__device__ int    g_deg_in [NNODE];
__device__ int    g_deg_out[NNODE];
__device__ int    g_cursor [NNODE];
__device__ int    g_ptr    [NNODE + 1];          // padded CSR row ptr by dst
__device__ __align__(16) unsigned g_csr[EPAD];   // (fp16 ns_src << 16) | src
__device__ float  g_norm_src[NNODE];
__device__ float  g_norm_dst[NNODE];
__device__ int    g_work;                        // k_agg work-stealing counter
__device__ int    g_bar_cnt;                     // prep phase barrier counter

// Packed 2xfp32 FMA (Blackwell FFMA2 — only reachable via PTX f32x2)
__device__ __forceinline__ unsigned long long ffma2(
    unsigned long long a, unsigned long long b, unsigned long long c) {
    unsigned long long d;
    asm("fma.rn.f32x2 %0, %1, %2, %3;" : "=l"(d) : "l"(a), "l"(b), "l"(c));
    return d;
}

// Phase barrier for the PREPB resident blocks. Not a deadlock risk: prep
// blocks are blockIdx 0..119 (all wave-1 resident), y-blocks never wait.
__device__ __forceinline__ void prep_bar(int target) {
    __syncthreads();
    if (threadIdx.x == 0) {
        __threadfence();
        atomicAdd(&g_bar_cnt, 1);
        while (atomicAdd(&g_bar_cnt, 0) < target) __nanosleep(64);
    }
    __syncthreads();
}

// build half2(ns, ns) from packed CSR word (ns fp16 bits in [31:16])
__device__ __forceinline__ __half2 mkns2(unsigned u) {
    unsigned r = (u & 0xFFFF0000u) | (u >> 16);
    return *reinterpret_cast<__half2*>(&r);
}

// ---------------------------------------------------------------------------
// K1: ONE kernel = prep chain (120 barriered blocks) + y'-GEMM (942 blocks).
// y branch: thread = (16 c' columns) x (4 bt) -> each LDS.128 of W (smem,
// broadcast) feeds 8 FFMA2; kernel LDS total halved vs R14, LDG/FMA same.
// W from smem (R15 constant-memory path regressed: LDC GPR-dest floor=8).
// y' = xW (UNNORMALIZED; norm_src applied in k_agg via packed fp16 ns).
// ---------------------------------------------------------------------------
__global__ __launch_bounds__(256, 2)
void k_prep_y(const float* __restrict__ x, const float* __restrict__ W,
              const int* __restrict__ src, const int* __restrict__ dst) {
    if (blockIdx.x < PREPB) {
        // ================= prep branch =================
        const int tid  = threadIdx.x;
        const int gtid = blockIdx.x * 256 + tid;

        // phase A: degree histograms (distributed global atomics)
        for (int e = gtid; e < EDGES; e += PREPB * 256) {
            atomicAdd(&g_deg_out[src[e]], 1);
            atomicAdd(&g_deg_in [dst[e]], 1);
        }
        prep_bar(PREPB);

        // phase B: block 0 only — norms + padded exclusive scan
        if (blockIdx.x == 0) {
            __shared__ int s_wsum[8];
            const int lane = tid & 31;
            const int warp = tid >> 5;

            if (tid == 0) g_work = 0;

            for (int i = tid; i < NNODE; i += 256) {
                g_norm_src[i] = rsqrtf((float)max(g_deg_out[i], 1));
                g_norm_dst[i] = rsqrtf((float)max(g_deg_in [i], 1));
            }

            // scan of pad-4 degrees: 20 nodes/thread (256*20 = 5120)
            const int base = tid * 20;
            int pd[20];
            int tsum = 0;
            #pragma unroll
            for (int k = 0; k < 20; k++) {
                int dg = (base + k < NNODE) ? g_deg_in[base + k] : 0;
                pd[k] = (dg + 3) & ~3;
                tsum += pd[k];
            }
            int incl = tsum;
            #pragma unroll
            for (int off = 1; off < 32; off <<= 1) {
                int t = __shfl_up_sync(0xffffffffu, incl, off);
                if (lane >= off) incl += t;
            }
            if (lane == 31) s_wsum[warp] = incl;
            __syncthreads();
            if (tid == 0) {
                int r = 0;
                #pragma unroll
                for (int w = 0; w < 8; w++) { int t = s_wsum[w]; s_wsum[w] = r; r += t; }
            }
            __syncthreads();

            int run = s_wsum[warp] + incl - tsum;
            #pragma unroll
            for (int k = 0; k < 20; k++) {
                int idx = base + k;
                if (idx < NNODE) { g_ptr[idx] = run; run += pd[k]; }
            }
            if (tid == (NNODE + 19) / 20 - 1) g_ptr[NNODE] = run;
        }
        prep_bar(2 * PREPB);

        // phase C: scatter (pack fp16 norm_src into bits [31:16]) + pad fill
        for (int e = gtid; e < EDGES; e += PREPB * 256) {
            int s = src[e], d = dst[e];
            int pos = __ldcg(&g_ptr[d]) + atomicAdd(&g_cursor[d], 1);
            unsigned nsb = (unsigned)__half_as_ushort(
                               __float2half_rn(__ldcg(&g_norm_src[s])));
            g_csr[pos] = (unsigned)s | (nsb << 16);
        }
        for (int i = gtid; i < NNODE; i += PREPB * 256) {
            int p  = __ldcg(&g_ptr[i]);
            int dg = __ldcg(&g_deg_in[i]);
            int pad = (dg + 3) & ~3;
            for (int j = dg; j < pad; j++) g_csr[p + j] = NNODE;  // ns=0, zero row
        }
        return;
    }

    // ================= y' branch (no prep dependency) =================
    __shared__ __align__(16) float2 Ws2[CC * CC / 2];
    int tid = threadIdx.x;
    int tx = tid & 31, ty = tid >> 5;
    for (int i = tid; i < CC * CC / 2; i += 256)
        Ws2[i] = reinterpret_cast<const float2*>(W)[i];
    __syncthreads();

    int yb  = blockIdx.x - PREPB;
    int nt  = yb % NTILES;
    int btt = yb / NTILES;           // 0..5, 16 bt each
    int n   = nt * 32 + tx;
    if (n >= NNODE) return;

    const int h      = ty & 1;       // c' half: columns [h*16, h*16+16)
    const int bp     = ty >> 1;      // bt quad 0..3
    const int btbase = btt * 16 + bp * 4;

    const size_t cstride = (size_t)TT * NNODE;
    const float* xp[4];
    #pragma unroll
    for (int k = 0; k < 4; k++) {
        int bt = btbase + k;
        int b = bt / TT, t = bt - b * TT;
        xp[k] = x + ((size_t)b * CC * TT) * NNODE + (size_t)t * NNODE + n;
    }

    unsigned long long acc[4][8];
    #pragma unroll
    for (int k = 0; k < 4; k++)
        #pragma unroll
        for (int j = 0; j < 8; j++) acc[k][j] = 0ull;

    // software-pipelined c-loop: 16 chunks of 2, double-buffered x loads
    float xa[4][2], xn[4][2];
    #pragma unroll
    for (int k = 0; k < 4; k++) {
        xa[k][0] = __ldcs(xp[k]);
        xa[k][1] = __ldcs(xp[k] + cstride);
        xn[k][0] = 0.0f; xn[k][1] = 0.0f;
    }

    #pragma unroll
    for (int ch = 0; ch < 16; ch++) {
        if (ch < 15) {
            #pragma unroll
            for (int k = 0; k < 4; k++) {
                xn[k][0] = __ldcs(xp[k] + (size_t)(ch * 2 + 2) * cstride);
                xn[k][1] = __ldcs(xp[k] + (size_t)(ch * 2 + 3) * cstride);
            }
        }
        #pragma unroll
        for (int kc = 0; kc < 2; kc++) {
            int c = ch * 2 + kc;
            // 16 W floats for this (c, h): 4 LDS.128 shared across 4 bt
            const ulonglong2* wr =
                reinterpret_cast<const ulonglong2*>(Ws2 + c * (CC / 2) + h * 8);
            ulonglong2 w0 = wr[0], w1 = wr[1], w2 = wr[2], w3 = wr[3];
            #pragma unroll
            for (int k = 0; k < 4; k++) {
                unsigned long long xv;
                asm("mov.b64 %0, {%1, %1};" : "=l"(xv) : "f"(xa[k][kc]));
                acc[k][0] = ffma2(xv, w0.x, acc[k][0]);
                acc[k][1] = ffma2(xv, w0.y, acc[k][1]);
                acc[k][2] = ffma2(xv, w1.x, acc[k][2]);
                acc[k][3] = ffma2(xv, w1.y, acc[k][3]);
                acc[k][4] = ffma2(xv, w2.x, acc[k][4]);
                acc[k][5] = ffma2(xv, w2.y, acc[k][5]);
                acc[k][6] = ffma2(xv, w3.x, acc[k][6]);
                acc[k][7] = ffma2(xv, w3.y, acc[k][7]);
            }
        }
        #pragma unroll
        for (int k = 0; k < 4; k++) { xa[k][0] = xn[k][0]; xa[k][1] = xn[k][1]; }
    }

    // pack fp16 (unnormalized) and store: 16 c' x 4 bt = 8 uint4
    #pragma unroll
    for (int k = 0; k < 4; k++) {
        unsigned o[8];
        #pragma unroll
        for (int j = 0; j < 8; j++) {
            float lo, hi;
            asm("mov.b64 {%0, %1}, %2;" : "=f"(lo), "=f"(hi) : "l"(acc[k][j]));
            __half2 hh = __floats2half2_rn(lo, hi);
            o[j] = *reinterpret_cast<unsigned*>(&hh);
        }
        uint4* yp = reinterpret_cast<uint4*>(
            g_y + (size_t)n * FF + (size_t)(btbase + k) * CC + h * 16);
        yp[0] = make_uint4(o[0], o[1], o[2], o[3]);
        yp[1] = make_uint4(o[4], o[5], o[6], o[7]);
    }
}

// ---------------------------------------------------------------------------
// K2: persistent work-stealing aggregation.
// agg[d] = norm_dst[d] * sum_e ns_src(e) * y'[src(e)]
// 8-edge main loop (8-deep MLP), two independent 4-edge HFMA2 chains with
// per-edge ns from the packed CSR word. fp32 upconvert per chain; 4-edge
// tail. Zeroes counters + barrier counter for next replay.
// ---------------------------------------------------------------------------
__global__ __launch_bounds__(384)
void k_agg() {
    __shared__ int s_d;
    int tid = threadIdx.x;
    if (blockIdx.x == 0 && tid == 0) g_bar_cnt = 0;   // reset prep barrier

    while (true) {
        if (tid == 0) s_d = atomicAdd(&g_work, 1);
        __syncthreads();
        int d = s_d;
        __syncthreads();
        if (d >= NNODE) return;

        if (tid == 0) {
            g_deg_in[d] = 0;
            g_deg_out[d] = 0;
            g_cursor[d] = 0;
        }

        int beg = g_ptr[d], end = g_ptr[d + 1];   // multiple of 4, 16B-aligned

        float2 acc[4];
        #pragma unroll
        for (int j = 0; j < 4; j++) acc[j] = make_float2(0.f, 0.f);

        int g0 = beg;
        for (; g0 + 8 <= end; g0 += 8) {
            uint4 i0 = *reinterpret_cast<const uint4*>(&g_csr[g0]);
            uint4 i1 = *reinterpret_cast<const uint4*>(&g_csr[g0 + 4]);
            unsigned u[8] = { i0.x, i0.y, i0.z, i0.w, i1.x, i1.y, i1.z, i1.w };
            uint4 v[8];
            #pragma unroll
            for (int k = 0; k < 8; k++)
                v[k] = reinterpret_cast<const uint4*>(
                           g_y + (size_t)(u[k] & 0xFFFFu) * FF)[tid];
            __half2 ha[4], hb[4];
            #pragma unroll
            for (int j = 0; j < 4; j++) {
                ha[j] = __floats2half2_rn(0.f, 0.f);
                hb[j] = __floats2half2_rn(0.f, 0.f);
            }
            #pragma unroll
            for (int k = 0; k < 4; k++) {
                __half2 nA = mkns2(u[k]);
                __half2 nB = mkns2(u[k + 4]);
                #pragma unroll
                for (int j = 0; j < 4; j++) {
                    ha[j] = __hfma2(*reinterpret_cast<const __half2*>(&(&v[k].x)[j]),
                                    nA, ha[j]);
                    hb[j] = __hfma2(*reinterpret_cast<const __half2*>(&(&v[k+4].x)[j]),
                                    nB, hb[j]);
                }
            }
            #pragma unroll
            for (int j = 0; j < 4; j++) {
                float2 fa = __half22float2(ha[j]);
                float2 fb = __half22float2(hb[j]);
                acc[j].x += fa.x + fb.x;
                acc[j].y += fa.y + fb.y;
            }
        }
        if (g0 < end) {            // tail: one group of 4
            uint4 i0 = *reinterpret_cast<const uint4*>(&g_csr[g0]);
            unsigned u[4] = { i0.x, i0.y, i0.z, i0.w };
            uint4 v[4];
            #pragma unroll
            for (int k = 0; k < 4; k++)
                v[k] = reinterpret_cast<const uint4*>(
                           g_y + (size_t)(u[k] & 0xFFFFu) * FF)[tid];
            #pragma unroll
            for (int j = 0; j < 4; j++) {
                __half2 h = __floats2half2_rn(0.f, 0.f);
                #pragma unroll
                for (int k = 0; k < 4; k++)
                    h = __hfma2(*reinterpret_cast<const __half2*>(&(&v[k].x)[j]),
                                mkns2(u[k]), h);
                float2 f = __half22float2(h);
                acc[j].x += f.x; acc[j].y += f.y;
            }
        }

        float nd = g_norm_dst[d];
        __half2 o[4];
        #pragma unroll
        for (int j = 0; j < 4; j++)
            o[j] = __floats2half2_rn(acc[j].x * nd, acc[j].y * nd);
        uint4 pack;
        pack.x = *reinterpret_cast<unsigned*>(&o[0]);
        pack.y = *reinterpret_cast<unsigned*>(&o[1]);
        pack.z = *reinterpret_cast<unsigned*>(&o[2]);
        pack.w = *reinterpret_cast<unsigned*>(&o[3]);
        reinterpret_cast<uint4*>(g_agg + (size_t)d * FF)[tid] = pack;
    }
}

// ---------------------------------------------------------------------------
// K3: out[b,c,t,n] = relu(x[b,c,t,n] + bias[c] + agg[n][b][t][c])
// ---------------------------------------------------------------------------
#define ONODES 256
__global__ __launch_bounds__(512, 3)
void k_out(const float* __restrict__ x, const float* __restrict__ bias,
           float* __restrict__ out) {
    __shared__ float s[CC][ONODES + 4];
    int bt = blockIdx.y;
    int b = bt / TT, t = bt - b * TT;
    int n0 = blockIdx.x * ONODES;
    int tid = threadIdx.y * 64 + threadIdx.x;

    {
        int nl   = tid >> 1;
        int part = tid & 1;
        int n = n0 + nl;
        if (n < NNODE) {
            const uint4* ar =
                reinterpret_cast<const uint4*>(g_agg + (size_t)n * FF + (size_t)bt * CC);
            #pragma unroll
            for (int q = 0; q < 2; q++) {
                uint4 v = ar[part * 2 + q];
                int c0 = part * 16 + q * 8;
                const unsigned* u = &v.x;
                #pragma unroll
                for (int j = 0; j < 4; j++) {
                    float2 f = __half22float2(*reinterpret_cast<const __half2*>(&u[j]));
                    s[c0 + 2*j    ][nl] = f.x;
                    s[c0 + 2*j + 1][nl] = f.y;
                }
            }
        }
    }
    __syncthreads();

    int n4 = threadIdx.x * 4;
    int n = n0 + n4;
    if (n < NNODE) {
        #pragma unroll
        for (int k = 0; k < 4; k++) {
            int c = threadIdx.y + k * 8;
            float bc = bias[c];
            size_t idx = (((size_t)b * CC + c) * TT + t) * NNODE + n;
            float4 xv = __ldcs(reinterpret_cast<const float4*>(x + idx));
            float4 av = *reinterpret_cast<const float4*>(&s[c][n4]);
            float4 r;
            r.x = fmaxf(xv.x + bc + av.x, 0.f);
            r.y = fmaxf(xv.y + bc + av.y, 0.f);
            r.z = fmaxf(xv.z + bc + av.z, 0.f);
            r.w = fmaxf(xv.w + bc + av.w, 0.f);
            __stcs(reinterpret_cast<float4*>(out + idx), r);
        }
    }
}

// ---------------------------------------------------------------------------
// Launch: 3 kernels
// ---------------------------------------------------------------------------
extern "C" void kernel_launch(void* const* d_in, const int* in_sizes, int n_in,
                              void* d_out, int out_size) {
    const float* x    = (const float*)d_in[0];  // [B, C, T, N]
    const float* W    = (const float*)d_in[1];  // [C, C]
    const float* bias = (const float*)d_in[2];  // [C]
    const int*   src  = (const int*)d_in[3];    // [E]
    const int*   dst  = (const int*)d_in[4];    // [E]
    float*       out  = (float*)d_out;          // [B, C, T, N]

    k_prep_y<<<PREPB + YBLOCKS, 256>>>(x, W, src, dst);
    k_agg<<<AGGBLOCKS, 384>>>();
    k_out<<<dim3((NNODE + ONODES - 1) / ONODES, BT), dim3(64, 8)>>>(x, bias, out);
}